// round 15
// baseline (speedup 1.0000x reference)
#include <cuda_runtime.h>
#include <cuda_fp16.h>
#include <cstdint>

#define N_NODES 100000
#define N_FEAT  128
#define N_EDGES 1600000
#define SCAN_CHUNK 1024
#define NBLK ((N_NODES + SCAN_CHUNK - 1) / SCAN_CHUNK)   // 98
#define APAD 72

// Scratch (__device__ globals: allocation-free).
__device__ int      g_degi[N_NODES];
__device__ int      g_rowstart[N_NODES];
__device__ int      g_cursor[N_NODES];
__device__ int      g_bsum[128];
__device__ int      g_srcs[N_EDGES];
__device__ float    g_dinv[N_NODES];
__device__ uint32_t g_BfragH[8 * 16 * 32 * 2];       // fp16 W frags (half2 each)
__device__ __half   g_xwh[(size_t)N_NODES * N_FEAT]; // (x@W^T)*dinv[row], fp16

// ---------------------------------------------------------------------------
// 1) fused: zero degree counters + pack W into fp16 m16n8k16 B-fragments.
//    uidx = ((kc*2 + h)*32 + lane)*16 + (nc&7)*2 + reg   (R14 layout, verified)
__global__ void k_init_bpack(const float* __restrict__ W) {
    const int t = blockIdx.x * blockDim.x + threadIdx.x;
    if (t < N_NODES) g_degi[t] = 0;
    if (t < 8 * 16 * 32) {
        const int lane = t & 31;
        const int nc   = (t >> 5) & 15;
        const int kc   = t >> 9;
        const int g  = lane >> 2;
        const int tg = lane & 3;
        const int k = kc * 16 + tg * 2;
        const int n = nc * 8 + g;
        const __half2 b0 = __floats2half2_rn(W[n * N_FEAT + k],     W[n * N_FEAT + k + 1]);
        const __half2 b1 = __floats2half2_rn(W[n * N_FEAT + k + 8], W[n * N_FEAT + k + 9]);
        const int base = ((kc * 2 + (nc >> 3)) * 32 + lane) * 16 + (nc & 7) * 2;
        g_BfragH[base + 0] = *reinterpret_cast<const uint32_t*>(&b0);
        g_BfragH[base + 1] = *reinterpret_cast<const uint32_t*>(&b1);
    }
}

// 2) degree count
__global__ void k_deg_count(const int* __restrict__ col) {
    int e = blockIdx.x * blockDim.x + threadIdx.x;
    if (e < N_EDGES) atomicAdd(&g_degi[col[e]], 1);
}

// 3) scan stage 1 (+ dinv)
__global__ void k_scan1() {
    __shared__ int sh[256];
    const int t = threadIdx.x;
    const int base = blockIdx.x * SCAN_CHUNK + t * 4;
    int v[4], s = 0;
    #pragma unroll
    for (int i = 0; i < 4; ++i) {
        int idx = base + i;
        v[i] = (idx < N_NODES) ? g_degi[idx] : 0;
        if (idx < N_NODES) g_dinv[idx] = rsqrtf((float)(v[i] + 1));
        s += v[i];
    }
    sh[t] = s; __syncthreads();
    #pragma unroll
    for (int off = 1; off < 256; off <<= 1) {
        int add = (t >= off) ? sh[t - off] : 0;
        __syncthreads();
        sh[t] += add;
        __syncthreads();
    }
    if (t == 255) g_bsum[blockIdx.x] = sh[255];
    int run = sh[t] - s;
    #pragma unroll
    for (int i = 0; i < 4; ++i) {
        int idx = base + i;
        if (idx < N_NODES) g_rowstart[idx] = run;
        run += v[i];
    }
}

// ---------------------------------------------------------------------------
#define MMA_F16(acc, a0, a1, a2, a3, b0, b1)                                   \
    asm volatile("mma.sync.aligned.m16n8k16.row.col.f32.f16.f16.f32 "          \
                 "{%0,%1,%2,%3}, {%4,%5,%6,%7}, {%8,%9}, {%0,%1,%2,%3};"       \
                 : "+f"(acc[0]), "+f"(acc[1]), "+f"(acc[2]), "+f"(acc[3])      \
                 : "r"(a0), "r"(a1), "r"(a2), "r"(a3), "r"(b0), "r"(b1))

// 4) GEMM (profiled): g_xwh = half((x @ W^T) * dinv[row]).
//    fp16 2-term split; conversion fully hoisted into staging.
//    smem = fragment-ordered uint arrays: pair pp of kc at pos (pp&3)*2+(pp>>2)
//    Mainloop per kc: 4 LDS.64 (A hi/lo x 2 rows) + 4 LDG.128 (B) + 16 MMA.
__global__ __launch_bounds__(256) void k_gemm(const float* __restrict__ x) {
    __shared__ uint32_t shi[64][APAD];                 // 18.4 KB
    __shared__ uint32_t slo[64][APAD];                 // 18.4 KB
    const int t    = threadIdx.x;
    const int warp = t >> 5;
    const int lane = t & 31;
    const int row0  = blockIdx.x * 64;
    const int nrows = min(64, N_NODES - row0);

    // Staging: float4 -> 2 half2 pairs (hi) + 2 residual pairs (lo),
    // scattered to fragment positions. Once per block; feeds 128 MMAs/warp.
    const float4* src = reinterpret_cast<const float4*>(x + (size_t)row0 * N_FEAT);
    for (int idx = t; idx < nrows * 32; idx += 256) {
        const int r  = idx >> 5, c4 = idx & 31;
        const float4 v = src[idx];
        const __half2 h0 = __floats2half2_rn(v.x, v.y);
        const __half2 h1 = __floats2half2_rn(v.z, v.w);
        const float2 e0 = __half22float2(h0), e1 = __half22float2(h1);
        const __half2 q0 = __floats2half2_rn(v.x - e0.x, v.y - e0.y);
        const __half2 q1 = __floats2half2_rn(v.z - e1.x, v.w - e1.y);
        const int kc  = c4 >> 2;
        const int pp0 = (2 * c4) & 7, pp1 = pp0 + 1;
        const int o0  = kc * 8 + (pp0 & 3) * 2 + (pp0 >> 2);
        const int o1  = kc * 8 + (pp1 & 3) * 2 + (pp1 >> 2);
        shi[r][o0] = *reinterpret_cast<const uint32_t*>(&h0);
        shi[r][o1] = *reinterpret_cast<const uint32_t*>(&h1);
        slo[r][o0] = *reinterpret_cast<const uint32_t*>(&q0);
        slo[r][o1] = *reinterpret_cast<const uint32_t*>(&q1);
    }
    __syncthreads();

    const int g   = lane >> 2;
    const int tg  = lane & 3;
    const int rb  = (warp & 3) * 16;
    const int h   = warp >> 2;        // N-half: nc0 = h*8
    const int nc0 = h * 8;

    float acc[8][4];
    #pragma unroll
    for (int j = 0; j < 8; ++j)
        acc[j][0] = acc[j][1] = acc[j][2] = acc[j][3] = 0.f;

    // B: per kc, 4 uint4 at ((kc*2 + h)*32 + lane)*4  (uint4 units)
    const uint4* bp = reinterpret_cast<const uint4*>(g_BfragH)
                      + ((size_t)h * 32 + lane) * 4;

    uint4 bcur[4];
    #pragma unroll
    for (int j = 0; j < 4; ++j) bcur[j] = bp[j];

    #pragma unroll
    for (int kc = 0; kc < 8; ++kc) {
        // A fragments: {a0,a2} from row rb+g, {a1,a3} from row rb+g+8.
        const uint2 ahr0 = *reinterpret_cast<const uint2*>(&shi[rb + g][kc * 8 + tg * 2]);
        const uint2 ahr1 = *reinterpret_cast<const uint2*>(&shi[rb + g + 8][kc * 8 + tg * 2]);
        const uint2 alr0 = *reinterpret_cast<const uint2*>(&slo[rb + g][kc * 8 + tg * 2]);
        const uint2 alr1 = *reinterpret_cast<const uint2*>(&slo[rb + g + 8][kc * 8 + tg * 2]);

        uint4 bnxt[4];
        if (kc < 7) {
            #pragma unroll
            for (int j = 0; j < 4; ++j) bnxt[j] = bp[(kc + 1) * 256 + j];
        }

        #pragma unroll
        for (int j = 0; j < 4; ++j) {
            const uint32_t b00 = bcur[j].x, b01 = bcur[j].y;   // nc = 2j
            const uint32_t b10 = bcur[j].z, b11 = bcur[j].w;   // nc = 2j+1
            MMA_F16(acc[2*j],     ahr0.x, ahr1.x, ahr0.y, ahr1.y, b00, b01);
            MMA_F16(acc[2*j],     alr0.x, alr1.x, alr0.y, alr1.y, b00, b01);
            MMA_F16(acc[2*j + 1], ahr0.x, ahr1.x, ahr0.y, ahr1.y, b10, b11);
            MMA_F16(acc[2*j + 1], alr0.x, alr1.x, alr0.y, alr1.y, b10, b11);
        }
        if (kc < 7) {
            #pragma unroll
            for (int j = 0; j < 4; ++j) bcur[j] = bnxt[j];
        }
    }

    // Epilogue: c0/c1 -> (row0+rb+g, col/col+1); c2/c3 -> (+8 rows).
    const int r0 = row0 + rb + g;
    const int r1 = r0 + 8;
    const float d0 = (r0 < N_NODES) ? g_dinv[r0] : 0.f;
    const float d1 = (r1 < N_NODES) ? g_dinv[r1] : 0.f;
    #pragma unroll
    for (int j = 0; j < 8; ++j) {
        const int col = (nc0 + j) * 8 + tg * 2;
        if (r0 < N_NODES)
            *reinterpret_cast<__half2*>(&g_xwh[(size_t)r0 * N_FEAT + col]) =
                __floats2half2_rn(acc[j][0] * d0, acc[j][1] * d0);
        if (r1 < N_NODES)
            *reinterpret_cast<__half2*>(&g_xwh[(size_t)r1 * N_FEAT + col]) =
                __floats2half2_rn(acc[j][2] * d1, acc[j][3] * d1);
    }
}

// 5) fused scan stages 2+3
__global__ void k_scan23() {
    __shared__ int sh[128];
    const int t = threadIdx.x;
    int v = 0;
    if (t < 128) { v = (t < NBLK) ? g_bsum[t] : 0; sh[t] = v; }
    __syncthreads();
    #pragma unroll
    for (int off = 1; off < 128; off <<= 1) {
        int add = 0;
        if (t < 128 && t >= off) add = sh[t - off];
        __syncthreads();
        if (t < 128) sh[t] += add;
        __syncthreads();
    }
    if (t < 128) sh[t] -= v;
    __syncthreads();
    const int i = blockIdx.x * blockDim.x + t;
    if (i < N_NODES) {
        int rs = g_rowstart[i] + sh[i >> 10];
        g_rowstart[i] = rs;
        g_cursor[i]   = rs;
    }
}

// 6) bucket-fill
__global__ void k_fill(const int* __restrict__ ei) {
    int e = blockIdx.x * blockDim.x + threadIdx.x;
    if (e < N_EDGES) {
        int c = ei[N_EDGES + e];
        int pos = atomicAdd(&g_cursor[c], 1);
        g_srcs[pos] = ei[e];
    }
}

// ---------------------------------------------------------------------------
// 7) Pull aggregation: one warp per target; fp16 rows, fp32 accumulation.
__global__ __launch_bounds__(256) void k_gather(const float* __restrict__ b,
                                                float* __restrict__ out) {
    const int warp = (blockIdx.x * blockDim.x + threadIdx.x) >> 5;
    const int lane = threadIdx.x & 31;
    if (warp >= N_NODES) return;
    const int c = warp;

    const int base = g_rowstart[c];
    const int cnt  = g_degi[c];

    float4 a0 = make_float4(0.f,0.f,0.f,0.f), a1 = a0, a2 = a0, a3 = a0;
    const uint2* xw = reinterpret_cast<const uint2*>(g_xwh);   // 8B = 4 halves

    int i = 0;
    for (; i + 4 <= cnt; i += 4) {
        const int s0 = g_srcs[base + i + 0];
        const int s1 = g_srcs[base + i + 1];
        const int s2 = g_srcs[base + i + 2];
        const int s3 = g_srcs[base + i + 3];
        const uint2 v0 = xw[(size_t)s0 * 32 + lane];
        const uint2 v1 = xw[(size_t)s1 * 32 + lane];
        const uint2 v2 = xw[(size_t)s2 * 32 + lane];
        const uint2 v3 = xw[(size_t)s3 * 32 + lane];
        {
            const float2 p = __half22float2(*(const __half2*)&v0.x);
            const float2 q = __half22float2(*(const __half2*)&v0.y);
            a0.x += p.x; a0.y += p.y; a0.z += q.x; a0.w += q.y;
        }
        {
            const float2 p = __half22float2(*(const __half2*)&v1.x);
            const float2 q = __half22float2(*(const __half2*)&v1.y);
            a1.x += p.x; a1.y += p.y; a1.z += q.x; a1.w += q.y;
        }
        {
            const float2 p = __half22float2(*(const __half2*)&v2.x);
            const float2 q = __half22float2(*(const __half2*)&v2.y);
            a2.x += p.x; a2.y += p.y; a2.z += q.x; a2.w += q.y;
        }
        {
            const float2 p = __half22float2(*(const __half2*)&v3.x);
            const float2 q = __half22float2(*(const __half2*)&v3.y);
            a3.x += p.x; a3.y += p.y; a3.z += q.x; a3.w += q.y;
        }
    }
    for (; i < cnt; ++i) {
        const int s = g_srcs[base + i];
        const uint2 v = xw[(size_t)s * 32 + lane];
        const float2 p = __half22float2(*(const __half2*)&v.x);
        const float2 q = __half22float2(*(const __half2*)&v.y);
        a0.x += p.x; a0.y += p.y; a0.z += q.x; a0.w += q.y;
    }

    const uint2 vs = xw[(size_t)c * 32 + lane];
    const float2 sp = __half22float2(*(const __half2*)&vs.x);
    const float2 sq = __half22float2(*(const __half2*)&vs.y);
    float4 acc = make_float4(a0.x + a1.x + a2.x + a3.x + sp.x,
                             a0.y + a1.y + a2.y + a3.y + sp.y,
                             a0.z + a1.z + a2.z + a3.z + sq.x,
                             a0.w + a1.w + a2.w + a3.w + sq.y);
    const float nc = g_dinv[c];
    const float4 bv = reinterpret_cast<const float4*>(b)[lane];
    reinterpret_cast<float4*>(out + (size_t)c * N_FEAT)[lane] =
        make_float4(acc.x * nc + bv.x, acc.y * nc + bv.y,
                    acc.z * nc + bv.z, acc.w * nc + bv.w);
}

// ---------------------------------------------------------------------------
extern "C" void kernel_launch(void* const* d_in, const int* in_sizes, int n_in,
                              void* d_out, int out_size) {
    const float* x  = (const float*)d_in[0];
    const int*   ei = (const int*)  d_in[1];
    const float* W  = (const float*)d_in[2];
    const float* b  = (const float*)d_in[3];
    float* out = (float*)d_out;

    k_init_bpack<<<(N_NODES + 255) / 256, 256>>>(W);               // 1
    k_deg_count <<<(N_EDGES + 255) / 256, 256>>>(ei + N_EDGES);    // 2
    k_scan1     <<<NBLK, 256>>>();                                 // 3 (dinv ready)
    k_gemm      <<<(N_NODES + 63) / 64, 256>>>(x);                 // 4 (profiled)
    k_scan23    <<<(N_NODES + 255) / 256, 256>>>();                // 5
    k_fill      <<<(N_EDGES + 255) / 256, 256>>>(ei);              // 6
    k_gather    <<<(N_NODES * 32 + 255) / 256, 256>>>(b, out);     // 7
}

// round 16
// speedup vs baseline: 1.0483x; 1.0483x over previous
#include <cuda_runtime.h>
#include <cuda_fp16.h>
#include <cstdint>

#define N_NODES 100000
#define N_FEAT  128
#define N_EDGES 1600000
#define SCAN_CHUNK 1024
#define NBLK ((N_NODES + SCAN_CHUNK - 1) / SCAN_CHUNK)   // 98
#define APAD 72

// Scratch (__device__ globals: allocation-free).
__device__ int      g_degi[N_NODES];
__device__ int      g_rowstart[N_NODES];
__device__ int      g_cursor[N_NODES];
__device__ int      g_bsum[128];
__device__ int      g_srcs[N_EDGES];
__device__ float    g_dinv[N_NODES];
__device__ uint32_t g_BfragH[8 * 16 * 32 * 2];       // fp16 W frags (half2 each)
__device__ __half   g_xwh[(size_t)N_NODES * N_FEAT]; // (x@W^T)*dinv[row], fp16

// ---------------------------------------------------------------------------
// 1) fused: zero degree counters + pack W into fp16 m16n8k16 B-fragments.
//    uidx = ((kc*2 + h)*32 + lane)*16 + (nc&7)*2 + reg   (R14 layout, verified)
__global__ void k_init_bpack(const float* __restrict__ W) {
    const int t = blockIdx.x * blockDim.x + threadIdx.x;
    if (t < N_NODES) g_degi[t] = 0;
    if (t < 8 * 16 * 32) {
        const int lane = t & 31;
        const int nc   = (t >> 5) & 15;
        const int kc   = t >> 9;
        const int g  = lane >> 2;
        const int tg = lane & 3;
        const int k = kc * 16 + tg * 2;
        const int n = nc * 8 + g;
        const __half2 b0 = __floats2half2_rn(W[n * N_FEAT + k],     W[n * N_FEAT + k + 1]);
        const __half2 b1 = __floats2half2_rn(W[n * N_FEAT + k + 8], W[n * N_FEAT + k + 9]);
        const int base = ((kc * 2 + (nc >> 3)) * 32 + lane) * 16 + (nc & 7) * 2;
        g_BfragH[base + 0] = *reinterpret_cast<const uint32_t*>(&b0);
        g_BfragH[base + 1] = *reinterpret_cast<const uint32_t*>(&b1);
    }
}

// 2) degree count, 4 edges/thread (int4 loads)
__global__ void k_deg_count(const int* __restrict__ col) {
    const int q = blockIdx.x * blockDim.x + threadIdx.x;
    if (q < N_EDGES / 4) {
        const int4 c4 = reinterpret_cast<const int4*>(col)[q];
        atomicAdd(&g_degi[c4.x], 1);
        atomicAdd(&g_degi[c4.y], 1);
        atomicAdd(&g_degi[c4.z], 1);
        atomicAdd(&g_degi[c4.w], 1);
    }
}

// 3) scan stage 1 (+ dinv)
__global__ void k_scan1() {
    __shared__ int sh[256];
    const int t = threadIdx.x;
    const int base = blockIdx.x * SCAN_CHUNK + t * 4;
    int v[4], s = 0;
    #pragma unroll
    for (int i = 0; i < 4; ++i) {
        int idx = base + i;
        v[i] = (idx < N_NODES) ? g_degi[idx] : 0;
        if (idx < N_NODES) g_dinv[idx] = rsqrtf((float)(v[i] + 1));
        s += v[i];
    }
    sh[t] = s; __syncthreads();
    #pragma unroll
    for (int off = 1; off < 256; off <<= 1) {
        int add = (t >= off) ? sh[t - off] : 0;
        __syncthreads();
        sh[t] += add;
        __syncthreads();
    }
    if (t == 255) g_bsum[blockIdx.x] = sh[255];
    int run = sh[t] - s;
    #pragma unroll
    for (int i = 0; i < 4; ++i) {
        int idx = base + i;
        if (idx < N_NODES) g_rowstart[idx] = run;
        run += v[i];
    }
}

// ---------------------------------------------------------------------------
#define MMA_F16(acc, a0, a1, a2, a3, b0, b1)                                   \
    asm volatile("mma.sync.aligned.m16n8k16.row.col.f32.f16.f16.f32 "          \
                 "{%0,%1,%2,%3}, {%4,%5,%6,%7}, {%8,%9}, {%0,%1,%2,%3};"       \
                 : "+f"(acc[0]), "+f"(acc[1]), "+f"(acc[2]), "+f"(acc[3])      \
                 : "r"(a0), "r"(a1), "r"(a2), "r"(a3), "r"(b0), "r"(b1))

// 4) GEMM (profiled): g_xwh = half((x @ W^T) * dinv[row]).
//    SINGLE-term fp16 (no lo correction): per kc = 2 LDS.64 + 4 LDG.128 + 8 MMA.
//    A converted to fragment-ordered fp16 smem during staging (R15 scheme).
__global__ __launch_bounds__(256) void k_gemm(const float* __restrict__ x) {
    __shared__ uint32_t shi[64][APAD];                 // 18.4 KB
    const int t    = threadIdx.x;
    const int warp = t >> 5;
    const int lane = t & 31;
    const int row0  = blockIdx.x * 64;
    const int nrows = min(64, N_NODES - row0);

    const float4* src = reinterpret_cast<const float4*>(x + (size_t)row0 * N_FEAT);
    for (int idx = t; idx < nrows * 32; idx += 256) {
        const int r  = idx >> 5, c4 = idx & 31;
        const float4 v = src[idx];
        const __half2 h0 = __floats2half2_rn(v.x, v.y);
        const __half2 h1 = __floats2half2_rn(v.z, v.w);
        const int kc  = c4 >> 2;
        const int pp0 = (2 * c4) & 7, pp1 = pp0 + 1;
        const int o0  = kc * 8 + (pp0 & 3) * 2 + (pp0 >> 2);
        const int o1  = kc * 8 + (pp1 & 3) * 2 + (pp1 >> 2);
        shi[r][o0] = *reinterpret_cast<const uint32_t*>(&h0);
        shi[r][o1] = *reinterpret_cast<const uint32_t*>(&h1);
    }
    __syncthreads();

    const int g   = lane >> 2;
    const int tg  = lane & 3;
    const int rb  = (warp & 3) * 16;
    const int h   = warp >> 2;        // N-half: nc0 = h*8
    const int nc0 = h * 8;

    float acc[8][4];
    #pragma unroll
    for (int j = 0; j < 8; ++j)
        acc[j][0] = acc[j][1] = acc[j][2] = acc[j][3] = 0.f;

    const uint4* bp = reinterpret_cast<const uint4*>(g_BfragH)
                      + ((size_t)h * 32 + lane) * 4;

    uint4 bcur[4];
    #pragma unroll
    for (int j = 0; j < 4; ++j) bcur[j] = bp[j];

    #pragma unroll
    for (int kc = 0; kc < 8; ++kc) {
        const uint2 ahr0 = *reinterpret_cast<const uint2*>(&shi[rb + g][kc * 8 + tg * 2]);
        const uint2 ahr1 = *reinterpret_cast<const uint2*>(&shi[rb + g + 8][kc * 8 + tg * 2]);

        uint4 bnxt[4];
        if (kc < 7) {
            #pragma unroll
            for (int j = 0; j < 4; ++j) bnxt[j] = bp[(kc + 1) * 256 + j];
        }

        #pragma unroll
        for (int j = 0; j < 4; ++j) {
            MMA_F16(acc[2*j],     ahr0.x, ahr1.x, ahr0.y, ahr1.y, bcur[j].x, bcur[j].y);
            MMA_F16(acc[2*j + 1], ahr0.x, ahr1.x, ahr0.y, ahr1.y, bcur[j].z, bcur[j].w);
        }
        if (kc < 7) {
            #pragma unroll
            for (int j = 0; j < 4; ++j) bcur[j] = bnxt[j];
        }
    }

    // Epilogue: c0/c1 -> (row0+rb+g, col/col+1); c2/c3 -> (+8 rows).
    const int r0 = row0 + rb + g;
    const int r1 = r0 + 8;
    const float d0 = (r0 < N_NODES) ? g_dinv[r0] : 0.f;
    const float d1 = (r1 < N_NODES) ? g_dinv[r1] : 0.f;
    #pragma unroll
    for (int j = 0; j < 8; ++j) {
        const int col = (nc0 + j) * 8 + tg * 2;
        if (r0 < N_NODES)
            *reinterpret_cast<__half2*>(&g_xwh[(size_t)r0 * N_FEAT + col]) =
                __floats2half2_rn(acc[j][0] * d0, acc[j][1] * d0);
        if (r1 < N_NODES)
            *reinterpret_cast<__half2*>(&g_xwh[(size_t)r1 * N_FEAT + col]) =
                __floats2half2_rn(acc[j][2] * d1, acc[j][3] * d1);
    }
}

// 5) fused scan stages 2+3
__global__ void k_scan23() {
    __shared__ int sh[128];
    const int t = threadIdx.x;
    int v = 0;
    if (t < 128) { v = (t < NBLK) ? g_bsum[t] : 0; sh[t] = v; }
    __syncthreads();
    #pragma unroll
    for (int off = 1; off < 128; off <<= 1) {
        int add = 0;
        if (t < 128 && t >= off) add = sh[t - off];
        __syncthreads();
        if (t < 128) sh[t] += add;
        __syncthreads();
    }
    if (t < 128) sh[t] -= v;
    __syncthreads();
    const int i = blockIdx.x * blockDim.x + t;
    if (i < N_NODES) {
        int rs = g_rowstart[i] + sh[i >> 10];
        g_rowstart[i] = rs;
        g_cursor[i]   = rs;
    }
}

// 6) bucket-fill, 4 edges/thread (int4 loads)
__global__ void k_fill(const int* __restrict__ ei) {
    const int q = blockIdx.x * blockDim.x + threadIdx.x;
    if (q < N_EDGES / 4) {
        const int4 s4 = reinterpret_cast<const int4*>(ei)[q];
        const int4 c4 = reinterpret_cast<const int4*>(ei + N_EDGES)[q];
        g_srcs[atomicAdd(&g_cursor[c4.x], 1)] = s4.x;
        g_srcs[atomicAdd(&g_cursor[c4.y], 1)] = s4.y;
        g_srcs[atomicAdd(&g_cursor[c4.z], 1)] = s4.z;
        g_srcs[atomicAdd(&g_cursor[c4.w], 1)] = s4.w;
    }
}

// ---------------------------------------------------------------------------
// 7) Pull aggregation: one warp per target; fp16 rows, fp32 accumulation.
__global__ __launch_bounds__(256) void k_gather(const float* __restrict__ b,
                                                float* __restrict__ out) {
    const int warp = (blockIdx.x * blockDim.x + threadIdx.x) >> 5;
    const int lane = threadIdx.x & 31;
    if (warp >= N_NODES) return;
    const int c = warp;

    const int base = g_rowstart[c];
    const int cnt  = g_degi[c];

    float4 a0 = make_float4(0.f,0.f,0.f,0.f), a1 = a0, a2 = a0, a3 = a0;
    const uint2* xw = reinterpret_cast<const uint2*>(g_xwh);   // 8B = 4 halves

    int i = 0;
    for (; i + 4 <= cnt; i += 4) {
        const int s0 = g_srcs[base + i + 0];
        const int s1 = g_srcs[base + i + 1];
        const int s2 = g_srcs[base + i + 2];
        const int s3 = g_srcs[base + i + 3];
        const uint2 v0 = xw[(size_t)s0 * 32 + lane];
        const uint2 v1 = xw[(size_t)s1 * 32 + lane];
        const uint2 v2 = xw[(size_t)s2 * 32 + lane];
        const uint2 v3 = xw[(size_t)s3 * 32 + lane];
        {
            const float2 p = __half22float2(*(const __half2*)&v0.x);
            const float2 q = __half22float2(*(const __half2*)&v0.y);
            a0.x += p.x; a0.y += p.y; a0.z += q.x; a0.w += q.y;
        }
        {
            const float2 p = __half22float2(*(const __half2*)&v1.x);
            const float2 q = __half22float2(*(const __half2*)&v1.y);
            a1.x += p.x; a1.y += p.y; a1.z += q.x; a1.w += q.y;
        }
        {
            const float2 p = __half22float2(*(const __half2*)&v2.x);
            const float2 q = __half22float2(*(const __half2*)&v2.y);
            a2.x += p.x; a2.y += p.y; a2.z += q.x; a2.w += q.y;
        }
        {
            const float2 p = __half22float2(*(const __half2*)&v3.x);
            const float2 q = __half22float2(*(const __half2*)&v3.y);
            a3.x += p.x; a3.y += p.y; a3.z += q.x; a3.w += q.y;
        }
    }
    for (; i < cnt; ++i) {
        const int s = g_srcs[base + i];
        const uint2 v = xw[(size_t)s * 32 + lane];
        const float2 p = __half22float2(*(const __half2*)&v.x);
        const float2 q = __half22float2(*(const __half2*)&v.y);
        a0.x += p.x; a0.y += p.y; a0.z += q.x; a0.w += q.y;
    }

    const uint2 vs = xw[(size_t)c * 32 + lane];
    const float2 sp = __half22float2(*(const __half2*)&vs.x);
    const float2 sq = __half22float2(*(const __half2*)&vs.y);
    float4 acc = make_float4(a0.x + a1.x + a2.x + a3.x + sp.x,
                             a0.y + a1.y + a2.y + a3.y + sp.y,
                             a0.z + a1.z + a2.z + a3.z + sq.x,
                             a0.w + a1.w + a2.w + a3.w + sq.y);
    const float nc = g_dinv[c];
    const float4 bv = reinterpret_cast<const float4*>(b)[lane];
    reinterpret_cast<float4*>(out + (size_t)c * N_FEAT)[lane] =
        make_float4(acc.x * nc + bv.x, acc.y * nc + bv.y,
                    acc.z * nc + bv.z, acc.w * nc + bv.w);
}

// ---------------------------------------------------------------------------
extern "C" void kernel_launch(void* const* d_in, const int* in_sizes, int n_in,
                              void* d_out, int out_size) {
    const float* x  = (const float*)d_in[0];
    const int*   ei = (const int*)  d_in[1];
    const float* W  = (const float*)d_in[2];
    const float* b  = (const float*)d_in[3];
    float* out = (float*)d_out;

    k_init_bpack<<<(N_NODES + 255) / 256, 256>>>(W);               // 1
    k_deg_count <<<(N_EDGES / 4 + 255) / 256, 256>>>(ei + N_EDGES);// 2
    k_scan1     <<<NBLK, 256>>>();                                 // 3 (dinv ready)
    k_gemm      <<<(N_NODES + 63) / 64, 256>>>(x);                 // 4 (profiled)
    k_scan23    <<<(N_NODES + 255) / 256, 256>>>();                // 5
    k_fill      <<<(N_EDGES / 4 + 255) / 256, 256>>>(ei);          // 6
    k_gather    <<<(N_NODES * 32 + 255) / 256, 256>>>(b, out);     // 7
}